// round 5
// baseline (speedup 1.0000x reference)
#include <cuda_runtime.h>
#include <cuda_bf16.h>
#include <math.h>

// ---------------- problem constants ----------------
#define NB 32
#define HH 56
#define WW 56
#define CD 256
#define TOK (NB*HH*WW)          // 100352 tokens
#define HEADS 8
#define HDIM 32
#define HID 1024
#define WS 7
#define NWIN (TOK/(WS*WS))      // 2048 windows

typedef __nv_bfloat16 bf16;
typedef __nv_bfloat162 bf162;

// ---------------- scratch (static device globals; no runtime alloc) -------
__device__ __align__(16) bf16  g_qkv [(size_t)TOK * 3 * CD];
__device__ __align__(16) bf16  g_o   [(size_t)TOK * CD];
__device__ __align__(16) float g_x1  [(size_t)TOK * CD];
__device__ __align__(16) bf16  g_h1  [(size_t)TOK * HID];
__device__ __align__(16) float g_bias[8 * 64 * 64];
__device__ __align__(16) bf16  g_wq[3 * CD * CD];
__device__ __align__(16) bf16  g_wp[CD * CD];
__device__ __align__(16) bf16  g_w1[HID * CD];
__device__ __align__(16) bf16  g_w2[CD * HID];

// ---------------- one-shot fp32 -> bf16 conversion of all weights ----------
// float4 ranges: wq 49152 | wp 16384 | w1 65536 | w2 65536  (total 196608)
__global__ void wconv_all(const float* __restrict__ qkv_w,
                          const float* __restrict__ proj_w,
                          const float* __restrict__ ffn_w1,
                          const float* __restrict__ ffn_w2,
                          bf16* __restrict__ wq, bf16* __restrict__ wp,
                          bf16* __restrict__ w1, bf16* __restrict__ w2) {
    int i = blockIdx.x * 256 + threadIdx.x;
    if (i >= 196608) return;
    const float* src;
    bf16* dst;
    int j;
    if (i < 49152)        { src = qkv_w;  dst = wq; j = i; }
    else if (i < 65536)   { src = proj_w; dst = wp; j = i - 49152; }
    else if (i < 131072)  { src = ffn_w1; dst = w1; j = i - 65536; }
    else                  { src = ffn_w2; dst = w2; j = i - 131072; }
    float4 v = ((const float4*)src)[j];
    *(bf162*)&dst[j * 4]     = __floats2bfloat162_rn(v.x, v.y);
    *(bf162*)&dst[j * 4 + 2] = __floats2bfloat162_rn(v.z, v.w);
}

// ---------------- mma / cp.async helpers -----------------------------------
__device__ __forceinline__ void mma_bf16(float* c, const unsigned* a, const unsigned* b) {
    asm volatile(
        "mma.sync.aligned.m16n8k16.row.col.f32.bf16.bf16.f32 "
        "{%0,%1,%2,%3}, {%4,%5,%6,%7}, {%8,%9}, {%0,%1,%2,%3};\n"
        : "+f"(c[0]), "+f"(c[1]), "+f"(c[2]), "+f"(c[3])
        : "r"(a[0]), "r"(a[1]), "r"(a[2]), "r"(a[3]), "r"(b[0]), "r"(b[1]));
}

__device__ __forceinline__ void cpa16(void* smem_dst, const void* gsrc) {
    unsigned s = (unsigned)__cvta_generic_to_shared(smem_dst);
    asm volatile("cp.async.cg.shared.global [%0], [%1], 16;\n" :: "r"(s), "l"(gsrc));
}

// ---------------- bf16 GEMM, optional fused LayerNorm on A -----------------
// C[M,N] = act( LN?(A)[M,K] * W[N,K]^T + bias ) (+res)
// Exact tiles: M%128==0, N%128==0, K%32==0; LNA additionally requires K<=256
// (full channel row per tile — true for both LN call sites, K=256).
enum { EP_BIAS = 0, EP_BIAS_RES = 1, EP_BIAS_GELU = 2 };

#define SP40 40   // smem pitch (halves) — conflict-free fragment loads

template <int EP, bool LNA, typename OutT>
__global__ __launch_bounds__(256, 2) void hgemm(const void* __restrict__ Av,
                                                const bf16* __restrict__ W,
                                                const float* __restrict__ lng,
                                                const float* __restrict__ lnb,
                                                const float* __restrict__ bias,
                                                const float* __restrict__ res,
                                                OutT* __restrict__ C,
                                                int M, int N, int K) {
    __shared__ bf16 As[2][128][SP40];
    __shared__ bf16 Bs[2][128][SP40];
    __shared__ float sg[256], sb[256], rm[128], ri[128];

    int tid = threadIdx.x;
    int bm = blockIdx.y * 128;
    int bn = blockIdx.x * 128;
    int warp = tid >> 5, lane = tid & 31;
    int g = lane >> 2, tig = lane & 3;
    int warpM = warp >> 2;
    int warpN = warp & 3;
    int lrow = tid >> 2;         // 0..63
    int lcol = (tid & 3) * 8;    // halves / floats: 0,8,16,24

    const float* Af = (const float*)Av;
    const bf16*  Ah = (const bf16*)Av;
    const bf16*  Wptr = W + (size_t)(bn + lrow) * K + lcol;

    if (LNA) {
        // ---- per-row LN stats (partials staged in sg/sb) ----
        {
            int row = tid >> 1, half = tid & 1;
            const float* rp = Af + (size_t)(bm + row) * K + half * (K >> 1);
            float s = 0.f, q = 0.f;
            for (int i = 0; i < (K >> 1); i += 4) {
                float4 v = *(const float4*)(rp + i);
                s += v.x + v.y + v.z + v.w;
                q += v.x * v.x + v.y * v.y + v.z * v.z + v.w * v.w;
            }
            sg[tid] = s; sb[tid] = q;
        }
        __syncthreads();
        if (tid < 128) {
            float S = sg[2 * tid] + sg[2 * tid + 1];
            float Q = sb[2 * tid] + sb[2 * tid + 1];
            float rK = 1.f / (float)K;
            float m = S * rK;
            rm[tid] = m;
            ri[tid] = rsqrtf(Q * rK - m * m + 1e-5f);
        }
        __syncthreads();
        for (int i = tid; i < K; i += 256) { sg[i] = lng[i]; sb[i] = lnb[i]; }
    }

    float acc[4][4][4];
#pragma unroll
    for (int i = 0; i < 4; i++)
#pragma unroll
        for (int j = 0; j < 4; j++)
#pragma unroll
            for (int t = 0; t < 4; t++) acc[i][j][t] = 0.f;

    // ---- prologue: stage tile 0 ----
    if (LNA) {
        __syncthreads();   // sg/sb ready
#pragma unroll
        for (int r = 0; r < 2; r++) {
            int row = lrow + 64 * r;
            const float* rp = Af + (size_t)(bm + row) * K + lcol;
            float4 v0 = *(const float4*)(rp);
            float4 v1 = *(const float4*)(rp + 4);
            float m = rm[row], iv = ri[row];
            bf162 o0 = __floats2bfloat162_rn((v0.x - m) * iv * sg[lcol]     + sb[lcol],
                                             (v0.y - m) * iv * sg[lcol + 1] + sb[lcol + 1]);
            bf162 o1 = __floats2bfloat162_rn((v0.z - m) * iv * sg[lcol + 2] + sb[lcol + 2],
                                             (v0.w - m) * iv * sg[lcol + 3] + sb[lcol + 3]);
            bf162 o2 = __floats2bfloat162_rn((v1.x - m) * iv * sg[lcol + 4] + sb[lcol + 4],
                                             (v1.y - m) * iv * sg[lcol + 5] + sb[lcol + 5]);
            bf162 o3 = __floats2bfloat162_rn((v1.z - m) * iv * sg[lcol + 6] + sb[lcol + 6],
                                             (v1.w - m) * iv * sg[lcol + 7] + sb[lcol + 7]);
            bf162* d = (bf162*)&As[0][row][lcol];
            d[0] = o0; d[1] = o1; d[2] = o2; d[3] = o3;
        }
    } else {
        const bf16* Aptr = Ah + (size_t)(bm + lrow) * K + lcol;
        cpa16(&As[0][lrow][lcol],      Aptr);
        cpa16(&As[0][lrow + 64][lcol], Aptr + (size_t)64 * K);
    }
    cpa16(&Bs[0][lrow][lcol],      Wptr);
    cpa16(&Bs[0][lrow + 64][lcol], Wptr + (size_t)64 * K);
    asm volatile("cp.async.commit_group;\n");

    int niter = K / 32;
    for (int it = 0; it < niter; it++) {
        int cur = it & 1;
        float4 p00, p01, p10, p11;   // LNA prefetch regs
        int k0n = (it + 1) * 32;
        if (it + 1 < niter) {
            int nxt = cur ^ 1;
            if (LNA) {
                const float* rp0 = Af + (size_t)(bm + lrow) * K + k0n + lcol;
                const float* rp1 = Af + (size_t)(bm + lrow + 64) * K + k0n + lcol;
                p00 = *(const float4*)(rp0); p01 = *(const float4*)(rp0 + 4);
                p10 = *(const float4*)(rp1); p11 = *(const float4*)(rp1 + 4);
            } else {
                const bf16* Aptr = Ah + (size_t)(bm + lrow) * K + lcol;
                cpa16(&As[nxt][lrow][lcol],      Aptr + k0n);
                cpa16(&As[nxt][lrow + 64][lcol], Aptr + (size_t)64 * K + k0n);
            }
            cpa16(&Bs[nxt][lrow][lcol],      Wptr + k0n);
            cpa16(&Bs[nxt][lrow + 64][lcol], Wptr + (size_t)64 * K + k0n);
            asm volatile("cp.async.commit_group;\n");
            asm volatile("cp.async.wait_group 1;\n");
        } else {
            asm volatile("cp.async.wait_group 0;\n");
        }
        __syncthreads();

#pragma unroll
        for (int s = 0; s < 2; s++) {
            int kk = s * 16 + 2 * tig;
            unsigned af[4][4], bfr[4][2];
#pragma unroll
            for (int mt = 0; mt < 4; mt++) {
                int m = warpM * 64 + mt * 16 + g;
                af[mt][0] = *(const unsigned*)&As[cur][m][kk];
                af[mt][1] = *(const unsigned*)&As[cur][m + 8][kk];
                af[mt][2] = *(const unsigned*)&As[cur][m][kk + 8];
                af[mt][3] = *(const unsigned*)&As[cur][m + 8][kk + 8];
            }
#pragma unroll
            for (int nt = 0; nt < 4; nt++) {
                int n = warpN * 32 + nt * 8 + g;
                bfr[nt][0] = *(const unsigned*)&Bs[cur][n][kk];
                bfr[nt][1] = *(const unsigned*)&Bs[cur][n][kk + 8];
            }
#pragma unroll
            for (int mt = 0; mt < 4; mt++)
#pragma unroll
                for (int nt = 0; nt < 4; nt++)
                    mma_bf16(acc[mt][nt], af[mt], bfr[nt]);
        }

        if (LNA && it + 1 < niter) {
            int nxt = cur ^ 1;
#pragma unroll
            for (int r = 0; r < 2; r++) {
                int row = lrow + 64 * r;
                float4 v0 = r ? p10 : p00;
                float4 v1 = r ? p11 : p01;
                float m = rm[row], iv = ri[row];
                int c0 = k0n + lcol;
                bf162 o0 = __floats2bfloat162_rn((v0.x - m) * iv * sg[c0]     + sb[c0],
                                                 (v0.y - m) * iv * sg[c0 + 1] + sb[c0 + 1]);
                bf162 o1 = __floats2bfloat162_rn((v0.z - m) * iv * sg[c0 + 2] + sb[c0 + 2],
                                                 (v0.w - m) * iv * sg[c0 + 3] + sb[c0 + 3]);
                bf162 o2 = __floats2bfloat162_rn((v1.x - m) * iv * sg[c0 + 4] + sb[c0 + 4],
                                                 (v1.y - m) * iv * sg[c0 + 5] + sb[c0 + 5]);
                bf162 o3 = __floats2bfloat162_rn((v1.z - m) * iv * sg[c0 + 6] + sb[c0 + 6],
                                                 (v1.w - m) * iv * sg[c0 + 7] + sb[c0 + 7]);
                bf162* d = (bf162*)&As[nxt][row][lcol];
                d[0] = o0; d[1] = o1; d[2] = o2; d[3] = o3;
            }
        }
        __syncthreads();
    }

    // ---- epilogue ----
#pragma unroll
    for (int mt = 0; mt < 4; mt++) {
        int r0 = bm + warpM * 64 + mt * 16 + g;
#pragma unroll
        for (int nt = 0; nt < 4; nt++) {
            int c = bn + warpN * 32 + nt * 8 + 2 * tig;
            float2 bv = *(const float2*)&bias[c];
            float v0 = acc[mt][nt][0] + bv.x;
            float v1 = acc[mt][nt][1] + bv.y;
            float v2 = acc[mt][nt][2] + bv.x;
            float v3 = acc[mt][nt][3] + bv.y;
            if (EP == EP_BIAS_GELU) {
                v0 = 0.5f * v0 * (1.f + erff(v0 * 0.70710678118654752f));
                v1 = 0.5f * v1 * (1.f + erff(v1 * 0.70710678118654752f));
                v2 = 0.5f * v2 * (1.f + erff(v2 * 0.70710678118654752f));
                v3 = 0.5f * v3 * (1.f + erff(v3 * 0.70710678118654752f));
            }
            if (EP == EP_BIAS_RES) {
                float2 r0v = *(const float2*)&res[(size_t)r0 * N + c];
                float2 r1v = *(const float2*)&res[(size_t)(r0 + 8) * N + c];
                v0 += r0v.x; v1 += r0v.y; v2 += r1v.x; v3 += r1v.y;
            }
            if (sizeof(OutT) == 2) {
                *(bf162*)((bf16*)C + (size_t)r0 * N + c) = __floats2bfloat162_rn(v0, v1);
                *(bf162*)((bf16*)C + (size_t)(r0 + 8) * N + c) = __floats2bfloat162_rn(v2, v3);
            } else {
                *(float2*)((float*)C + (size_t)r0 * N + c) = make_float2(v0, v1);
                *(float2*)((float*)C + (size_t)(r0 + 8) * N + c) = make_float2(v2, v3);
            }
        }
    }
}

// ---------------- expand rel-pos bias into [8][64][64] with col mask -------
__global__ void bias_expand(const float* __restrict__ table,
                            float* __restrict__ bf) {
    int idx = blockIdx.x * 256 + threadIdx.x;
    if (idx >= 8 * 64 * 64) return;
    int h = idx >> 12;
    int r = (idx >> 6) & 63;
    int c = idx & 63;
    float v;
    if (c >= 49) v = -1e30f;
    else if (r >= 49) v = 0.f;
    else {
        int ri = r / 7, ci = r % 7, rj = c / 7, cj = c % 7;
        int rel = (ri - rj + 6) * 13 + (ci - cj + 6);
        v = table[rel * 8 + h];
    }
    bf[idx] = v;
}

// ---------------- bf16 tensor-core windowed attention ----------------------
#define QP 40
#define PP 72
__global__ __launch_bounds__(128) void attn_mma(const bf16* __restrict__ qkv,
                                                const float* __restrict__ bias_full,
                                                bf16* __restrict__ o) {
    __shared__ bf16 smem[64 * QP * 2 + 32 * PP];
    __shared__ int  TOF[64];
    bf16* SQ = smem;
    bf16* SK = smem + 64 * QP;
    bf16* SPm = smem;
    bf16* VT = smem + 64 * QP * 2;

    int bw   = blockIdx.x >> 3;
    int head = blockIdx.x & 7;
    int b  = bw >> 6;
    int wi = bw & 63;
    int wh = wi >> 3;
    int ww = wi & 7;
    int tid  = threadIdx.x;
    int warp = tid >> 5, lane = tid & 31;
    int g = lane >> 2, tig = lane & 3;

    if (tid < 64) {
        int n = tid;
        int r = n / 7, c = n - r * 7;
        TOF[n] = (n < 49) ? (b * 3136 + (wh * 7 + r) * 56 + ww * 7 + c) : 0;
    }
    __syncthreads();

    const int4 zero4 = make_int4(0, 0, 0, 0);
    for (int idx = tid; idx < 256; idx += 128) {
        int n = idx >> 2, seg = (idx & 3) * 8;
        int4 qv = zero4, kv = zero4;
        if (n < 49) {
            const bf16* base = qkv + (size_t)TOF[n] * 768 + head * 32 + seg;
            qv = *(const int4*)(base);
            kv = *(const int4*)(base + 256);
        }
        *(int4*)&SQ[n * QP + seg] = qv;
        *(int4*)&SK[n * QP + seg] = kv;
    }
    for (int idx = tid; idx < 2048; idx += 128) {
        int n = idx >> 5, d = idx & 31;
        bf16 val = __float2bfloat16(0.f);
        if (n < 49) val = qkv[(size_t)TOF[n] * 768 + 512 + head * 32 + d];
        VT[d * PP + n] = val;
    }
    __syncthreads();

    float accS[8][4];
#pragma unroll
    for (int nt = 0; nt < 8; nt++)
#pragma unroll
        for (int t = 0; t < 4; t++) accS[nt][t] = 0.f;

    int wrow = warp * 16;
#pragma unroll
    for (int ks = 0; ks < 2; ks++) {
        int kk = ks * 16 + 2 * tig;
        unsigned a[4];
        a[0] = *(const unsigned*)&SQ[(wrow + g) * QP + kk];
        a[1] = *(const unsigned*)&SQ[(wrow + g + 8) * QP + kk];
        a[2] = *(const unsigned*)&SQ[(wrow + g) * QP + kk + 8];
        a[3] = *(const unsigned*)&SQ[(wrow + g + 8) * QP + kk + 8];
#pragma unroll
        for (int nt = 0; nt < 8; nt++) {
            unsigned bfr[2];
            bfr[0] = *(const unsigned*)&SK[(nt * 8 + g) * QP + kk];
            bfr[1] = *(const unsigned*)&SK[(nt * 8 + g) * QP + kk + 8];
            mma_bf16(accS[nt], a, bfr);
        }
    }

    const float sc = 0.17677669529663687f;
    int r0 = wrow + g, r1 = wrow + g + 8;
    const float* bh = bias_full + head * 4096;
    float m0 = -1e30f, m1 = -1e30f;
#pragma unroll
    for (int nt = 0; nt < 8; nt++) {
        float2 b0 = *(const float2*)(bh + r0 * 64 + nt * 8 + 2 * tig);
        float2 b1 = *(const float2*)(bh + r1 * 64 + nt * 8 + 2 * tig);
        accS[nt][0] = accS[nt][0] * sc + b0.x;
        accS[nt][1] = accS[nt][1] * sc + b0.y;
        accS[nt][2] = accS[nt][2] * sc + b1.x;
        accS[nt][3] = accS[nt][3] * sc + b1.y;
        m0 = fmaxf(m0, fmaxf(accS[nt][0], accS[nt][1]));
        m1 = fmaxf(m1, fmaxf(accS[nt][2], accS[nt][3]));
    }
    m0 = fmaxf(m0, __shfl_xor_sync(0xffffffffu, m0, 1));
    m0 = fmaxf(m0, __shfl_xor_sync(0xffffffffu, m0, 2));
    m1 = fmaxf(m1, __shfl_xor_sync(0xffffffffu, m1, 1));
    m1 = fmaxf(m1, __shfl_xor_sync(0xffffffffu, m1, 2));

    float s0 = 0.f, s1 = 0.f;
#pragma unroll
    for (int nt = 0; nt < 8; nt++) {
        accS[nt][0] = __expf(accS[nt][0] - m0);
        accS[nt][1] = __expf(accS[nt][1] - m0);
        accS[nt][2] = __expf(accS[nt][2] - m1);
        accS[nt][3] = __expf(accS[nt][3] - m1);
        s0 += accS[nt][0] + accS[nt][1];
        s1 += accS[nt][2] + accS[nt][3];
    }
    s0 += __shfl_xor_sync(0xffffffffu, s0, 1);
    s0 += __shfl_xor_sync(0xffffffffu, s0, 2);
    s1 += __shfl_xor_sync(0xffffffffu, s1, 1);
    s1 += __shfl_xor_sync(0xffffffffu, s1, 2);
    float i0 = 1.f / s0, i1 = 1.f / s1;

    __syncthreads();
#pragma unroll
    for (int nt = 0; nt < 8; nt++) {
        *(bf162*)&SPm[r0 * PP + nt * 8 + 2 * tig] =
            __floats2bfloat162_rn(accS[nt][0] * i0, accS[nt][1] * i0);
        *(bf162*)&SPm[r1 * PP + nt * 8 + 2 * tig] =
            __floats2bfloat162_rn(accS[nt][2] * i1, accS[nt][3] * i1);
    }
    __syncthreads();

    float accO[4][4];
#pragma unroll
    for (int nt = 0; nt < 4; nt++)
#pragma unroll
        for (int t = 0; t < 4; t++) accO[nt][t] = 0.f;

#pragma unroll
    for (int ks = 0; ks < 4; ks++) {
        int kk = ks * 16 + 2 * tig;
        unsigned a[4];
        a[0] = *(const unsigned*)&SPm[(wrow + g) * PP + kk];
        a[1] = *(const unsigned*)&SPm[(wrow + g + 8) * PP + kk];
        a[2] = *(const unsigned*)&SPm[(wrow + g) * PP + kk + 8];
        a[3] = *(const unsigned*)&SPm[(wrow + g + 8) * PP + kk + 8];
#pragma unroll
        for (int nt = 0; nt < 4; nt++) {
            unsigned bfr[2];
            bfr[0] = *(const unsigned*)&VT[(nt * 8 + g) * PP + kk];
            bfr[1] = *(const unsigned*)&VT[(nt * 8 + g) * PP + kk + 8];
            mma_bf16(accO[nt], a, bfr);
        }
    }

    if (r0 < 49) {
        bf16* op = o + (size_t)TOF[r0] * 256 + head * 32;
#pragma unroll
        for (int nt = 0; nt < 4; nt++)
            *(bf162*)(op + nt * 8 + 2 * tig) = __floats2bfloat162_rn(accO[nt][0], accO[nt][1]);
    }
    if (r1 < 49) {
        bf16* op = o + (size_t)TOF[r1] * 256 + head * 32;
#pragma unroll
        for (int nt = 0; nt < 4; nt++)
            *(bf162*)(op + nt * 8 + 2 * tig) = __floats2bfloat162_rn(accO[nt][2], accO[nt][3]);
    }
}

// ---------------- launch ----------------
extern "C" void kernel_launch(void* const* d_in, const int* in_sizes, int n_in,
                              void* d_out, int out_size) {
    const float* x          = (const float*)d_in[0];
    const float* norm1_g    = (const float*)d_in[1];
    const float* norm1_b    = (const float*)d_in[2];
    const float* qkv_w      = (const float*)d_in[3];
    const float* qkv_b      = (const float*)d_in[4];
    const float* bias_table = (const float*)d_in[5];
    const float* proj_w     = (const float*)d_in[6];
    const float* proj_b     = (const float*)d_in[7];
    const float* norm2_g    = (const float*)d_in[8];
    const float* norm2_b    = (const float*)d_in[9];
    const float* ffn_w1     = (const float*)d_in[10];
    const float* ffn_b1     = (const float*)d_in[11];
    const float* ffn_w2     = (const float*)d_in[12];
    const float* ffn_b2     = (const float*)d_in[13];
    float* out = (float*)d_out;

    bf16 *qkv, *o, *h1, *wq, *wp, *w1, *w2;
    float *x1, *bf;
    cudaGetSymbolAddress((void**)&qkv, g_qkv);
    cudaGetSymbolAddress((void**)&o,   g_o);
    cudaGetSymbolAddress((void**)&x1,  g_x1);
    cudaGetSymbolAddress((void**)&h1,  g_h1);
    cudaGetSymbolAddress((void**)&bf,  g_bias);
    cudaGetSymbolAddress((void**)&wq,  g_wq);
    cudaGetSymbolAddress((void**)&wp,  g_wp);
    cudaGetSymbolAddress((void**)&w1,  g_w1);
    cudaGetSymbolAddress((void**)&w2,  g_w2);

    const int MT = TOK;  // 100352 = 784*128

    wconv_all<<<768, 256>>>(qkv_w, proj_w, ffn_w1, ffn_w2, wq, wp, w1, w2);
    bias_expand<<<(8 * 64 * 64 + 255) / 256, 256>>>(bias_table, bf);

    // QKV with fused LN1:  qkv = LN1(x) @ wq^T + b
    hgemm<EP_BIAS, true, bf16><<<dim3(768 / 128, MT / 128), 256>>>(
        x, wq, norm1_g, norm1_b, qkv_b, nullptr, qkv, MT, 768, 256);

    attn_mma<<<NWIN * HEADS, 128>>>(qkv, bf, o);

    // proj + residual(x) -> x1 (fp32)
    hgemm<EP_BIAS_RES, false, float><<<dim3(256 / 128, MT / 128), 256>>>(
        o, wp, nullptr, nullptr, proj_b, x, x1, MT, 256, 256);

    // FFN1 with fused LN2 + GELU: h1 = gelu(LN2(x1) @ w1^T + b1)
    hgemm<EP_BIAS_GELU, true, bf16><<<dim3(HID / 128, MT / 128), 256>>>(
        x1, w1, norm2_g, norm2_b, ffn_b1, nullptr, h1, MT, HID, 256);

    // FFN2 + residual(x1) -> out
    hgemm<EP_BIAS_RES, false, float><<<dim3(256 / 128, MT / 128), 256>>>(
        h1, w2, nullptr, nullptr, ffn_b2, x1, out, MT, 256, 1024);
}